// round 4
// baseline (speedup 1.0000x reference)
#include <cuda_runtime.h>
#include <math.h>
#include <cstdint>

#define BB 4
#define SSEQ 2048
#define DMODEL 1024
#define NHEAD 16
#define HDIM 64

__device__ float g_Q[(size_t)BB * NHEAD * SSEQ * HDIM];
__device__ float g_K[(size_t)BB * NHEAD * SSEQ * HDIM];
__device__ float g_V[(size_t)BB * NHEAD * SSEQ * HDIM];
__device__ float g_attn[(size_t)BB * SSEQ * DMODEL];

// ---------------------------------------------------------------------------
__device__ __forceinline__ uint32_t f2tf_u(float f) {
    uint32_t u;
    asm("cvt.rna.tf32.f32 %0, %1;" : "=r"(u) : "f"(f));
    return u;
}
__device__ __forceinline__ float f2tf(float f) { return __uint_as_float(f2tf_u(f)); }

__device__ __forceinline__ void mma8(float* c, const uint32_t* a, const uint32_t* b) {
    asm volatile(
        "mma.sync.aligned.m16n8k8.row.col.f32.tf32.tf32.f32 "
        "{%0,%1,%2,%3}, {%4,%5,%6,%7}, {%8,%9}, {%0,%1,%2,%3};"
        : "+f"(c[0]), "+f"(c[1]), "+f"(c[2]), "+f"(c[3])
        : "r"(a[0]), "r"(a[1]), "r"(a[2]), "r"(a[3]), "r"(b[0]), "r"(b[1]));
}

// exp(x), FFMA-pipe only. Hot path: args bounded (no clamp).
__device__ __forceinline__ float fexp(float x) {
    float y = x * 1.4426950408889634f;
    float t = y + 12582912.f;
    int   ki = __float_as_int(t) - 0x4B400000;
    float f = y - (t - 12582912.f);
    float r = fmaf(f, 0.0096181f, 0.0555041f);
    r = fmaf(r, f, 0.2402265f);
    r = fmaf(r, f, 0.6931472f);
    r = fmaf(r, f, 1.0f);
    return __int_as_float(__float_as_int(r) + (ki << 23));
}
__device__ __forceinline__ float fexp_s(float x) { return fexp(fmaxf(x, -80.f)); }

// ---------------------------------------------------------------------------
// tf32 tensor GEMM (unchanged from round 2): C = A @ W + bias
// ---------------------------------------------------------------------------
#define ASTR 20
#define BSTR 132

__global__ void __launch_bounds__(256) gemm_tc(
    const float* __restrict__ A, const float* __restrict__ W,
    const float* __restrict__ bias, float* __restrict__ C, int permute)
{
    __shared__ float As[2][128 * ASTR];
    __shared__ float Bs[2][16 * BSTR];

    const int tid = threadIdx.x, lane = tid & 31, wid = tid >> 5;
    const int gID = lane >> 2, tig = lane & 3;
    const int wm = wid >> 2, wn = wid & 3;
    const int m0 = blockIdx.y * 128, n0 = blockIdx.x * 128;

    const float* Ag = A + (size_t)m0 * DMODEL;
    const float* Bg = W + n0;

    float acc[4][4][4];
#pragma unroll
    for (int mt = 0; mt < 4; mt++)
#pragma unroll
        for (int nt = 0; nt < 4; nt++)
#pragma unroll
            for (int i = 0; i < 4; i++) acc[mt][nt][i] = 0.f;

    const int ar = tid >> 2, ac = (tid & 3) * 4;
    const int br = tid >> 5, bc = (tid & 31) * 4;

    float4 ra0, ra1, rb0, rb1;
    ra0 = *(const float4*)(Ag + (size_t)ar * DMODEL + ac);
    ra1 = *(const float4*)(Ag + (size_t)(ar + 64) * DMODEL + ac);
    rb0 = *(const float4*)(Bg + (size_t)br * DMODEL + bc);
    rb1 = *(const float4*)(Bg + (size_t)(br + 8) * DMODEL + bc);
    {
        float* pa = As[0]; float* pb = Bs[0];
        pa[ar * ASTR + ac + 0] = f2tf(ra0.x); pa[ar * ASTR + ac + 1] = f2tf(ra0.y);
        pa[ar * ASTR + ac + 2] = f2tf(ra0.z); pa[ar * ASTR + ac + 3] = f2tf(ra0.w);
        pa[(ar + 64) * ASTR + ac + 0] = f2tf(ra1.x); pa[(ar + 64) * ASTR + ac + 1] = f2tf(ra1.y);
        pa[(ar + 64) * ASTR + ac + 2] = f2tf(ra1.z); pa[(ar + 64) * ASTR + ac + 3] = f2tf(ra1.w);
        pb[br * BSTR + bc + 0] = f2tf(rb0.x); pb[br * BSTR + bc + 1] = f2tf(rb0.y);
        pb[br * BSTR + bc + 2] = f2tf(rb0.z); pb[br * BSTR + bc + 3] = f2tf(rb0.w);
        pb[(br + 8) * BSTR + bc + 0] = f2tf(rb1.x); pb[(br + 8) * BSTR + bc + 1] = f2tf(rb1.y);
        pb[(br + 8) * BSTR + bc + 2] = f2tf(rb1.z); pb[(br + 8) * BSTR + bc + 3] = f2tf(rb1.w);
    }
    __syncthreads();

    for (int ch = 0; ch < 64; ++ch) {
        const int buf = ch & 1;
        if (ch < 63) {
            const int kt = (ch + 1) * 16;
            ra0 = *(const float4*)(Ag + (size_t)ar * DMODEL + kt + ac);
            ra1 = *(const float4*)(Ag + (size_t)(ar + 64) * DMODEL + kt + ac);
            rb0 = *(const float4*)(Bg + (size_t)(kt + br) * DMODEL + bc);
            rb1 = *(const float4*)(Bg + (size_t)(kt + br + 8) * DMODEL + bc);
        }
        const float* pa = As[buf];
        const float* pb = Bs[buf];
#pragma unroll
        for (int kk = 0; kk < 2; ++kk) {
            uint32_t af[4][4], bf[4][2];
            const int ci = kk * 8 + tig;
#pragma unroll
            for (int mt = 0; mt < 4; ++mt) {
                const int r = wm * 64 + mt * 16 + gID;
                af[mt][0] = __float_as_uint(pa[r * ASTR + ci]);
                af[mt][1] = __float_as_uint(pa[(r + 8) * ASTR + ci]);
                af[mt][2] = __float_as_uint(pa[r * ASTR + ci + 4]);
                af[mt][3] = __float_as_uint(pa[(r + 8) * ASTR + ci + 4]);
            }
#pragma unroll
            for (int nt = 0; nt < 4; ++nt) {
                const int cn = wn * 32 + nt * 8 + gID;
                bf[nt][0] = __float_as_uint(pb[ci * BSTR + cn]);
                bf[nt][1] = __float_as_uint(pb[(ci + 4) * BSTR + cn]);
            }
#pragma unroll
            for (int mt = 0; mt < 4; ++mt)
#pragma unroll
                for (int nt = 0; nt < 4; ++nt)
                    mma8(acc[mt][nt], af[mt], bf[nt]);
        }
        if (ch < 63) {
            __syncthreads();
            float* pa2 = As[buf ^ 1]; float* pb2 = Bs[buf ^ 1];
            pa2[ar * ASTR + ac + 0] = f2tf(ra0.x); pa2[ar * ASTR + ac + 1] = f2tf(ra0.y);
            pa2[ar * ASTR + ac + 2] = f2tf(ra0.z); pa2[ar * ASTR + ac + 3] = f2tf(ra0.w);
            pa2[(ar + 64) * ASTR + ac + 0] = f2tf(ra1.x); pa2[(ar + 64) * ASTR + ac + 1] = f2tf(ra1.y);
            pa2[(ar + 64) * ASTR + ac + 2] = f2tf(ra1.z); pa2[(ar + 64) * ASTR + ac + 3] = f2tf(ra1.w);
            pb2[br * BSTR + bc + 0] = f2tf(rb0.x); pb2[br * BSTR + bc + 1] = f2tf(rb0.y);
            pb2[br * BSTR + bc + 2] = f2tf(rb0.z); pb2[br * BSTR + bc + 3] = f2tf(rb0.w);
            pb2[(br + 8) * BSTR + bc + 0] = f2tf(rb1.x); pb2[(br + 8) * BSTR + bc + 1] = f2tf(rb1.y);
            pb2[(br + 8) * BSTR + bc + 2] = f2tf(rb1.z); pb2[(br + 8) * BSTR + bc + 3] = f2tf(rb1.w);
            __syncthreads();
        }
    }

#pragma unroll
    for (int mt = 0; mt < 4; ++mt) {
        const int r0 = m0 + wm * 64 + mt * 16 + gID;
        const int r1 = r0 + 8;
#pragma unroll
        for (int nt = 0; nt < 4; ++nt) {
            const int c = n0 + wn * 32 + nt * 8 + tig * 2;
            const float b0 = bias[c], b1 = bias[c + 1];
            float2 v0 = make_float2(acc[mt][nt][0] + b0, acc[mt][nt][1] + b1);
            float2 v1 = make_float2(acc[mt][nt][2] + b0, acc[mt][nt][3] + b1);
            if (permute) {
                const int hh = c >> 6, dd = c & 63;
                const int b_0 = r0 >> 11, s_0 = r0 & 2047;
                const int b_1 = r1 >> 11, s_1 = r1 & 2047;
                *(float2*)(C + ((((size_t)(b_0 * NHEAD + hh)) * SSEQ + s_0) * HDIM + dd)) = v0;
                *(float2*)(C + ((((size_t)(b_1 * NHEAD + hh)) * SSEQ + s_1) * HDIM + dd)) = v1;
            } else {
                *(float2*)(C + (size_t)r0 * DMODEL + c) = v0;
                *(float2*)(C + (size_t)r1 * DMODEL + c) = v1;
            }
        }
    }
}

// ---------------------------------------------------------------------------
// FlashAttention-2 style: warp owns 16 full q-rows. S/P register-resident.
// 8 warps x 16 rows = 128 q-rows per block. KV block = 128.
// ---------------------------------------------------------------------------
#define QSTR 72   // stride mod 32 == 8 -> conflict-free fragment loads

__global__ void __launch_bounds__(256) attn_tc(
    const float* __restrict__ Q, const float* __restrict__ K,
    const float* __restrict__ V, float* __restrict__ Aout)
{
    extern __shared__ float smf[];
    float* Qs = smf;                  // 128 x QSTR (tf32, pre-scaled)
    float* Ks = Qs + 128 * QSTR;
    float* Vs = Ks + 128 * QSTR;

    const int tid = threadIdx.x, lane = tid & 31, wid = tid >> 5;
    const int gID = lane >> 2, tig = lane & 3;
    const int qb = blockIdx.x, h = blockIdx.y, b = blockIdx.z;

    const size_t bh = (size_t)(b * NHEAD + h) * SSEQ;
    const float* Qg = Q + (bh + (size_t)qb * 128) * HDIM;

    const int ldr = tid >> 4, ldc = (tid & 15) * 4;
#pragma unroll
    for (int p = 0; p < 8; ++p) {
        const int r = ldr + p * 16;
        float4 v = *(const float4*)(Qg + (size_t)r * HDIM + ldc);
        Qs[r * QSTR + ldc + 0] = f2tf(v.x * 0.125f);
        Qs[r * QSTR + ldc + 1] = f2tf(v.y * 0.125f);
        Qs[r * QSTR + ldc + 2] = f2tf(v.z * 0.125f);
        Qs[r * QSTR + ldc + 3] = f2tf(v.w * 0.125f);
    }

    const int row0 = wid * 16 + gID;        // this thread's row pair: row0, row0+8

    float m0 = -INFINITY, m1 = -INFINITY, l0 = 0.f, l1 = 0.f;
    float oacc[8][4];
#pragma unroll
    for (int nt = 0; nt < 8; nt++)
#pragma unroll
        for (int i = 0; i < 4; i++) oacc[nt][i] = 0.f;

    const int quad_base = lane & 0x1C;
    const int srcLo = quad_base | (tig >> 1);
    const int srcHi = quad_base | ((tig >> 1) + 2);
    const int odd = tig & 1;

    for (int kb = 0; kb < 16; ++kb) {
        __syncthreads();   // prior S/PV reads of Ks/Vs complete
        const float* Kg = K + (bh + (size_t)kb * 128) * HDIM;
        const float* Vg = V + (bh + (size_t)kb * 128) * HDIM;
#pragma unroll
        for (int p = 0; p < 8; ++p) {
            const int r = ldr + p * 16;
            float4 kv = *(const float4*)(Kg + (size_t)r * HDIM + ldc);
            float4 vv = *(const float4*)(Vg + (size_t)r * HDIM + ldc);
            Ks[r * QSTR + ldc + 0] = f2tf(kv.x); Ks[r * QSTR + ldc + 1] = f2tf(kv.y);
            Ks[r * QSTR + ldc + 2] = f2tf(kv.z); Ks[r * QSTR + ldc + 3] = f2tf(kv.w);
            Vs[r * QSTR + ldc + 0] = f2tf(vv.x); Vs[r * QSTR + ldc + 1] = f2tf(vv.y);
            Vs[r * QSTR + ldc + 2] = f2tf(vv.z); Vs[r * QSTR + ldc + 3] = f2tf(vv.w);
        }
        __syncthreads();

        // --- S = Q @ K^T : warp tile 16 x 128 (16 n-tiles), reg-resident ---
        float sacc[16][4];
#pragma unroll
        for (int nt = 0; nt < 16; nt++)
#pragma unroll
            for (int i = 0; i < 4; i++) sacc[nt][i] = 0.f;

#pragma unroll
        for (int kd = 0; kd < 8; ++kd) {
            const int ci = kd * 8 + tig;
            uint32_t af[4];
            af[0] = __float_as_uint(Qs[row0 * QSTR + ci]);
            af[1] = __float_as_uint(Qs[(row0 + 8) * QSTR + ci]);
            af[2] = __float_as_uint(Qs[row0 * QSTR + ci + 4]);
            af[3] = __float_as_uint(Qs[(row0 + 8) * QSTR + ci + 4]);
#pragma unroll
            for (int nt = 0; nt < 16; ++nt) {
                const int cn = nt * 8 + gID;
                uint32_t bf[2];
                bf[0] = __float_as_uint(Ks[cn * QSTR + ci]);
                bf[1] = __float_as_uint(Ks[cn * QSTR + ci + 4]);
                mma8(sacc[nt], af, bf);
            }
        }

        // --- online softmax, fully in registers (quad shfl reductions) ---
        float mx0 = -INFINITY, mx1 = -INFINITY;
#pragma unroll
        for (int nt = 0; nt < 16; ++nt) {
            mx0 = fmaxf(mx0, fmaxf(sacc[nt][0], sacc[nt][1]));
            mx1 = fmaxf(mx1, fmaxf(sacc[nt][2], sacc[nt][3]));
        }
        mx0 = fmaxf(mx0, __shfl_xor_sync(0xffffffffu, mx0, 1));
        mx0 = fmaxf(mx0, __shfl_xor_sync(0xffffffffu, mx0, 2));
        mx1 = fmaxf(mx1, __shfl_xor_sync(0xffffffffu, mx1, 1));
        mx1 = fmaxf(mx1, __shfl_xor_sync(0xffffffffu, mx1, 2));

        const float mn0 = fmaxf(m0, mx0), mn1 = fmaxf(m1, mx1);
        const float al0 = fexp_s(m0 - mn0), al1 = fexp_s(m1 - mn1);
        m0 = mn0; m1 = mn1;

        float ls0 = 0.f, ls1 = 0.f;
#pragma unroll
        for (int nt = 0; nt < 16; ++nt) {
            float p0 = fexp(sacc[nt][0] - mn0);
            float p1 = fexp(sacc[nt][1] - mn0);
            float p2 = fexp(sacc[nt][2] - mn1);
            float p3 = fexp(sacc[nt][3] - mn1);
            ls0 += p0 + p1; ls1 += p2 + p3;
            sacc[nt][0] = p0; sacc[nt][1] = p1; sacc[nt][2] = p2; sacc[nt][3] = p3;
        }
        ls0 += __shfl_xor_sync(0xffffffffu, ls0, 1);
        ls0 += __shfl_xor_sync(0xffffffffu, ls0, 2);
        ls1 += __shfl_xor_sync(0xffffffffu, ls1, 1);
        ls1 += __shfl_xor_sync(0xffffffffu, ls1, 2);
        l0 = l0 * al0 + ls0;
        l1 = l1 * al1 + ls1;

#pragma unroll
        for (int nt = 0; nt < 8; ++nt) {
            oacc[nt][0] *= al0; oacc[nt][1] *= al0;
            oacc[nt][2] *= al1; oacc[nt][3] *= al1;
        }

        // --- O += P @ V ; P fragments via quad shfl permute ---
#pragma unroll
        for (int ks = 0; ks < 16; ++ks) {
            float e0 = __shfl_sync(0xffffffffu, sacc[ks][0], srcLo);
            float e1 = __shfl_sync(0xffffffffu, sacc[ks][1], srcLo);
            float e2 = __shfl_sync(0xffffffffu, sacc[ks][2], srcLo);
            float e3 = __shfl_sync(0xffffffffu, sacc[ks][3], srcLo);
            float f0 = __shfl_sync(0xffffffffu, sacc[ks][0], srcHi);
            float f1 = __shfl_sync(0xffffffffu, sacc[ks][1], srcHi);
            float f2 = __shfl_sync(0xffffffffu, sacc[ks][2], srcHi);
            float f3 = __shfl_sync(0xffffffffu, sacc[ks][3], srcHi);
            uint32_t af[4];
            af[0] = f2tf_u(odd ? e1 : e0);
            af[1] = f2tf_u(odd ? e3 : e2);
            af[2] = f2tf_u(odd ? f1 : f0);
            af[3] = f2tf_u(odd ? f3 : f2);
            const int kr = ks * 8 + tig;
#pragma unroll
            for (int nt = 0; nt < 8; ++nt) {
                const int cn = nt * 8 + gID;
                uint32_t bf[2];
                bf[0] = __float_as_uint(Vs[kr * QSTR + cn]);
                bf[1] = __float_as_uint(Vs[(kr + 4) * QSTR + cn]);
                mma8(oacc[nt], af, bf);
            }
        }
    }

    // --- output: O / l -> [b][s][h*64+d] ---
    const float i0 = 1.f / l0, i1 = 1.f / l1;
    float* out0 = Aout + ((size_t)b * SSEQ + qb * 128 + row0) * DMODEL + h * HDIM;
    float* out1 = out0 + (size_t)8 * DMODEL;
#pragma unroll
    for (int nt = 0; nt < 8; ++nt) {
        const int c = nt * 8 + tig * 2;
        *(float2*)(out0 + c) = make_float2(oacc[nt][0] * i0, oacc[nt][1] * i0);
        *(float2*)(out1 + c) = make_float2(oacc[nt][2] * i1, oacc[nt][3] * i1);
    }
}

extern "C" void kernel_launch(void* const* d_in, const int* in_sizes, int n_in,
                              void* d_out, int out_size) {
    const float* X  = (const float*)d_in[0];
    const float* Wq = (const float*)d_in[1];
    const float* bq = (const float*)d_in[2];
    const float* Wk = (const float*)d_in[3];
    const float* bk = (const float*)d_in[4];
    const float* Wv = (const float*)d_in[5];
    const float* bv = (const float*)d_in[6];
    const float* Wo = (const float*)d_in[7];
    const float* bo = (const float*)d_in[8];
    float* out = (float*)d_out;

    void *qp, *kp, *vp, *ap;
    cudaGetSymbolAddress(&qp, g_Q);
    cudaGetSymbolAddress(&kp, g_K);
    cudaGetSymbolAddress(&vp, g_V);
    cudaGetSymbolAddress(&ap, g_attn);

    const int attn_smem = (3 * 128 * QSTR) * (int)sizeof(float);
    cudaFuncSetAttribute(attn_tc, cudaFuncAttributeMaxDynamicSharedMemorySize, attn_smem);

    dim3 gg(DMODEL / 128, (BB * SSEQ) / 128, 1);
    gemm_tc<<<gg, 256>>>(X, Wq, bq, (float*)qp, 1);
    gemm_tc<<<gg, 256>>>(X, Wk, bk, (float*)kp, 1);
    gemm_tc<<<gg, 256>>>(X, Wv, bv, (float*)vp, 1);
    attn_tc<<<dim3(SSEQ / 128, NHEAD, BB), 256, attn_smem>>>(
        (const float*)qp, (const float*)kp, (const float*)vp, (float*)ap);
    gemm_tc<<<gg, 256>>>((const float*)ap, Wo, bo, out, 0);
}